// round 1
// baseline (speedup 1.0000x reference)
#include <cuda_runtime.h>

// Breadth_45896020525813 — fused GNN layer:
//   P = x @ (W1a - W1b)^T ; Q = x @ W1b^T          (node-level, K1)
//   per edge: h = leaky(P[dst]+Q[src]+b1); msg = h@W2^T + b2 ; scatter-max(dst)
//   out = tanh(agg), empty segments -> 0
//
// Pipeline: init(-inf) -> histogram(dst) -> scan -> scatter (dst-grouped edge
// list) -> P/Q -> edge kernel (f32x2 FMA, warp segmented max, few atomics)
// -> tanh finalize.

typedef unsigned long long ull;

#define NMAX 50000
#define EMAX 800000

__device__ float g_P[NMAX * 64];
__device__ float g_Q[NMAX * 64];
__device__ int   g_src_s[EMAX];
__device__ int   g_dst_s[EMAX];
__device__ int   g_deg[NMAX];
__device__ int   g_cursor[NMAX];
__device__ int   g_is64;

__device__ __forceinline__ ull pack2(float lo, float hi) {
    ull r;
    asm("mov.b64 %0, {%1, %2};" : "=l"(r) : "f"(lo), "f"(hi));
    return r;
}
__device__ __forceinline__ void unpack2(ull v, float& lo, float& hi) {
    asm("mov.b64 {%0, %1}, %2;" : "=f"(lo), "=f"(hi) : "l"(v));
}
// packed fp32x2 FMA: acc = a*b + acc  (2 MACs / instr on the fma pipe)
__device__ __forceinline__ void fma2(ull& acc, ull a, ull b) {
    asm("fma.rn.f32x2 %0, %1, %2, %0;" : "+l"(acc) : "l"(a), "l"(b));
}

// ---------------------------------------------------------------- init
// out <- -inf bits, deg <- 0, and probe edge dtype (int64 vs int32):
// for int64 values < 2^31, every odd 32-bit word is 0.
__global__ void k_init(float* __restrict__ out, const int* __restrict__ ei_raw, int N) {
    int idx = blockIdx.x * blockDim.x + threadIdx.x;
    int tot4 = N * 16;  // N*64 floats as int4
    if (idx < tot4) {
        int4 v;
        v.x = v.y = v.z = v.w = 0xFF800000;  // -inf
        ((int4*)out)[idx] = v;
    }
    if (idx < N) g_deg[idx] = 0;
    if (idx == 0) {
        int z = 0;
#pragma unroll
        for (int t = 1; t < 64; t += 2) z |= ei_raw[t];
        g_is64 = (z == 0) ? 1 : 0;
    }
}

__device__ __forceinline__ int load_edge(const void* ei, size_t pos, int is64) {
    return is64 ? (int)((const long long*)ei)[pos] : ((const int*)ei)[pos];
}

// ---------------------------------------------------------------- histogram
__global__ void k_hist(const void* __restrict__ ei, int E) {
    int e = blockIdx.x * blockDim.x + threadIdx.x;
    if (e >= E) return;
    int is64 = g_is64;
    int dst = load_edge(ei, (size_t)E + e, is64);
    atomicAdd(&g_deg[dst], 1);
}

// ---------------------------------------------------------------- scan (1 block)
__global__ void k_scan(int n) {
    __shared__ int sums[1024];
    int tid = threadIdx.x;
    int chunk = (n + (int)blockDim.x - 1) / (int)blockDim.x;
    int start = tid * chunk;
    int end = min(start + chunk, n);
    int s = 0;
    for (int i = start; i < end; ++i) s += g_deg[i];
    sums[tid] = s;
    __syncthreads();
    for (int o = 1; o < (int)blockDim.x; o <<= 1) {
        int t = (tid >= o) ? sums[tid - o] : 0;
        __syncthreads();
        sums[tid] += t;
        __syncthreads();
    }
    int off = sums[tid] - s;  // exclusive prefix
    for (int i = start; i < end; ++i) {
        g_cursor[i] = off;
        off += g_deg[i];
    }
}

// ---------------------------------------------------------------- scatter (group by dst)
__global__ void k_scatter(const void* __restrict__ ei, int E) {
    int e = blockIdx.x * blockDim.x + threadIdx.x;
    if (e >= E) return;
    int is64 = g_is64;
    int src = load_edge(ei, (size_t)e, is64);
    int dst = load_edge(ei, (size_t)E + e, is64);
    int pos = atomicAdd(&g_cursor[dst], 1);
    g_src_s[pos] = src;
    g_dst_s[pos] = dst;
}

// ---------------------------------------------------------------- P,Q = x @ A^T, x @ B^T
// warp per node, lane owns output pair (2*lane, 2*lane+1), packed f32x2.
__global__ void k_pq(const float* __restrict__ x, const float* __restrict__ W1, int N) {
    __shared__ ull A2[64 * 32];  // [d][pair] : (W1a-W1b) transposed, k-pairs packed
    __shared__ ull B2[64 * 32];  // [d][pair] : W1b transposed
    int tid = threadIdx.x;
    for (int idx = tid; idx < 2048; idx += blockDim.x) {
        int d = idx >> 5, p = idx & 31;
        int k0 = 2 * p, k1 = 2 * p + 1;
        float w0a = W1[k0 * 128 + d], w0b = W1[k0 * 128 + 64 + d];
        float w1a = W1[k1 * 128 + d], w1b = W1[k1 * 128 + 64 + d];
        A2[idx] = pack2(w0a - w0b, w1a - w1b);
        B2[idx] = pack2(w0b, w1b);
    }
    __syncthreads();
    int lane = tid & 31;
    int warps = (gridDim.x * blockDim.x) >> 5;
    int gw = (blockIdx.x * blockDim.x + tid) >> 5;
    ull* P2 = (ull*)g_P;
    ull* Q2 = (ull*)g_Q;
    for (int n = gw; n < N; n += warps) {
        const float* xr = x + (size_t)n * 64;
        ull accP = 0ull, accQ = 0ull;  // (0.0f,0.0f)
#pragma unroll
        for (int d = 0; d < 64; d++) {
            float xv = __ldg(&xr[d]);  // warp-uniform -> broadcast
            ull x2 = pack2(xv, xv);
            fma2(accP, x2, A2[d * 32 + lane]);
            fma2(accQ, x2, B2[d * 32 + lane]);
        }
        P2[(size_t)n * 32 + lane] = accP;
        Q2[(size_t)n * 32 + lane] = accQ;
    }
}

// ---------------------------------------------------------------- main edge kernel
__global__ void __launch_bounds__(256) k_edge(
    const float* __restrict__ b1, const float* __restrict__ b2,
    const float* __restrict__ W2, float* __restrict__ out, int E)
{
    __shared__ __align__(16) ull W2s[64 * 32];  // row-major, d-pairs packed
    __shared__ __align__(16) float b1s[64];
    __shared__ float b2s[64];
    int tid = threadIdx.x;
    const ull* W2u = (const ull*)W2;
    for (int idx = tid; idx < 2048; idx += 256) W2s[idx] = W2u[idx];
    if (tid < 64) { b1s[tid] = b1[tid]; b2s[tid] = b2[tid]; }
    __syncthreads();

    int e = blockIdx.x * 256 + tid;
    if (e >= E) e = E - 1;  // duplicate last edge; max() makes this benign
    int i = g_dst_s[e];     // target (grouped -> non-decreasing within warp)
    int j = g_src_s[e];

    // h = leaky(P[i] + Q[j] + b1), packed as 32 f32x2 regs
    ull h2[32];
    const float4* Pr = (const float4*)(g_P + (size_t)i * 64);
    const float4* Qr = (const float4*)(g_Q + (size_t)j * 64);
    const float4* Br = (const float4*)b1s;
#pragma unroll
    for (int t = 0; t < 16; t++) {
        float4 a = Pr[t], q = Qr[t], c = Br[t];
        float s0 = a.x + q.x + c.x; s0 = s0 > 0.f ? s0 : 0.01f * s0;
        float s1 = a.y + q.y + c.y; s1 = s1 > 0.f ? s1 : 0.01f * s1;
        float s2 = a.z + q.z + c.z; s2 = s2 > 0.f ? s2 : 0.01f * s2;
        float s3 = a.w + q.w + c.w; s3 = s3 > 0.f ? s3 : 0.01f * s3;
        h2[2 * t]     = pack2(s0, s1);
        h2[2 * t + 1] = pack2(s2, s3);
    }

    // warp segment structure over sorted dst (monotone -> equality test valid)
    int lane = tid & 31;
    const unsigned FULL = 0xFFFFFFFFu;
    int p1  = __shfl_up_sync(FULL, i, 1);
    int p2  = __shfl_up_sync(FULL, i, 2);
    int p4  = __shfl_up_sync(FULL, i, 4);
    int p8  = __shfl_up_sync(FULL, i, 8);
    int p16 = __shfl_up_sync(FULL, i, 16);
    bool m1  = (lane >= 1)  && (p1 == i);
    bool m2  = (lane >= 2)  && (p2 == i);
    bool m4  = (lane >= 4)  && (p4 == i);
    bool m8  = (lane >= 8)  && (p8 == i);
    bool m16 = (lane >= 16) && (p16 == i);
    int nx = __shfl_down_sync(FULL, i, 1);
    bool tail = (lane == 31) || (nx != i);

    float* aggrow = out + (size_t)i * 64;
    const float4* aggrow4 = (const float4*)aggrow;

#pragma unroll 1
    for (int kq = 0; kq < 16; kq++) {
        float4 cur = aggrow4[kq];  // monotone-safe stale read
        float curv0 = cur.x, curv1 = cur.y, curv2 = cur.z, curv3 = cur.w;
#pragma unroll
        for (int kk = 0; kk < 4; kk++) {
            int k = kq * 4 + kk;
            ull acc0 = 0ull, acc1 = 0ull;
            const ulonglong2* wr = (const ulonglong2*)(W2s + k * 32);
#pragma unroll
            for (int t = 0; t < 16; t++) {
                ulonglong2 w = wr[t];  // LDS.128 broadcast
                fma2(acc0, h2[2 * t], w.x);
                fma2(acc1, h2[2 * t + 1], w.y);
            }
            float a0, a1, a2, a3;
            unpack2(acc0, a0, a1);
            unpack2(acc1, a2, a3);
            float v = (a0 + a2) + (a1 + a3) + b2s[k];

            // inclusive segmented max-scan; tail lane holds segment max
            float o;
            o = __shfl_up_sync(FULL, v, 1);  if (m1)  v = fmaxf(v, o);
            o = __shfl_up_sync(FULL, v, 2);  if (m2)  v = fmaxf(v, o);
            o = __shfl_up_sync(FULL, v, 4);  if (m4)  v = fmaxf(v, o);
            o = __shfl_up_sync(FULL, v, 8);  if (m8)  v = fmaxf(v, o);
            o = __shfl_up_sync(FULL, v, 16); if (m16) v = fmaxf(v, o);

            float curk = (kk == 0) ? curv0 : (kk == 1) ? curv1 : (kk == 2) ? curv2 : curv3;
            if (tail && v > curk) {
                // bit-trick float atomicMax (works for any sign, init = -inf)
                if (v >= 0.f)
                    atomicMax((int*)(aggrow + k), __float_as_int(v));
                else
                    atomicMin((unsigned int*)(aggrow + k), (unsigned int)__float_as_int(v));
            }
        }
    }
}

// ---------------------------------------------------------------- finalize: tanh / empty->0
__global__ void k_final(float* __restrict__ out, int total4) {
    int idx = blockIdx.x * blockDim.x + threadIdx.x;
    if (idx >= total4) return;
    const float NEG_INF = __int_as_float(0xFF800000);
    float4 v = ((float4*)out)[idx];
    v.x = (v.x == NEG_INF) ? 0.f : tanhf(v.x);
    v.y = (v.y == NEG_INF) ? 0.f : tanhf(v.y);
    v.z = (v.z == NEG_INF) ? 0.f : tanhf(v.z);
    v.w = (v.w == NEG_INF) ? 0.f : tanhf(v.w);
    ((float4*)out)[idx] = v;
}

// ---------------------------------------------------------------- launch
extern "C" void kernel_launch(void* const* d_in, const int* in_sizes, int n_in,
                              void* d_out, int out_size) {
    const float* x  = (const float*)d_in[0];
    const void*  ei = d_in[1];
    const float* W1 = (const float*)d_in[2];
    const float* b1 = (const float*)d_in[3];
    const float* W2 = (const float*)d_in[4];
    const float* b2 = (const float*)d_in[5];
    int N = in_sizes[0] / 64;
    int E = in_sizes[1] / 2;
    float* out = (float*)d_out;

    k_init<<<(N * 16 + 255) / 256, 256>>>(out, (const int*)ei, N);
    k_hist<<<(E + 255) / 256, 256>>>(ei, E);
    k_scan<<<1, 1024>>>(N);
    k_scatter<<<(E + 255) / 256, 256>>>(ei, E);
    k_pq<<<1024, 256>>>(x, W1, N);
    k_edge<<<(E + 255) / 256, 256>>>(b1, b2, W2, out, E);
    k_final<<<(N * 16 + 255) / 256, 256>>>(out, N * 16);
}

// round 2
// speedup vs baseline: 1.1175x; 1.1175x over previous
#include <cuda_runtime.h>
#include <math_constants.h>

// Breadth_45896020525813 — fused GNN layer (round 2):
//   P = x @ (W1a - W1b)^T + b1 ; Q = x @ W1b^T     (node-level)
//   per edge: h = leaky(P[dst]+Q[src]); msg = h@W2^T ; max over edges per dst
//   out = tanh(max + b2), empty rows -> 0
//
// k_edge: warp-per-dst CSR walk. W2 register-resident (lane owns output pair,
// 64 f32x2 regs), h staged 256B/edge via smem uniform reads. No atomics.

typedef unsigned long long ull;

#define NMAX 50000
#define EMAX 800000

__device__ float g_P[NMAX * 64];   // P + b1, pair-packed [n][32] ull view
__device__ float g_Q[NMAX * 64];
__device__ int   g_src_s[EMAX];    // src ids grouped by dst
__device__ int   g_deg[NMAX];
__device__ int   g_row[NMAX];      // CSR row start
__device__ int   g_cursor[NMAX];
__device__ int   g_is64;

__device__ __forceinline__ ull pack2(float lo, float hi) {
    ull r;
    asm("mov.b64 %0, {%1, %2};" : "=l"(r) : "f"(lo), "f"(hi));
    return r;
}
__device__ __forceinline__ void unpack2(ull v, float& lo, float& hi) {
    asm("mov.b64 {%0, %1}, %2;" : "=f"(lo), "=f"(hi) : "l"(v));
}
__device__ __forceinline__ void fma2(ull& acc, ull a, ull b) {
    asm("fma.rn.f32x2 %0, %1, %2, %0;" : "+l"(acc) : "l"(a), "l"(b));
}
__device__ __forceinline__ ull add2(ull a, ull b) {
    ull r;
    asm("add.rn.f32x2 %0, %1, %2;" : "=l"(r) : "l"(a), "l"(b));
    return r;
}

// ---------------------------------------------------------------- init
__global__ void k_init(const int* __restrict__ ei_raw, int N) {
    int idx = blockIdx.x * blockDim.x + threadIdx.x;
    if (idx < N) g_deg[idx] = 0;
    if (idx == 0) {
        int z = 0;
#pragma unroll
        for (int t = 1; t < 64; t += 2) z |= ei_raw[t];
        g_is64 = (z == 0) ? 1 : 0;
    }
}

__device__ __forceinline__ int load_edge(const void* ei, size_t pos, int is64) {
    return is64 ? (int)((const long long*)ei)[pos] : ((const int*)ei)[pos];
}

// ---------------------------------------------------------------- histogram
__global__ void k_hist(const void* __restrict__ ei, int E) {
    int e = blockIdx.x * blockDim.x + threadIdx.x;
    if (e >= E) return;
    int dst = load_edge(ei, (size_t)E + e, g_is64);
    atomicAdd(&g_deg[dst], 1);
}

// ---------------------------------------------------------------- scan (1 block)
__global__ void k_scan(int n) {
    __shared__ int sums[1024];
    int tid = threadIdx.x;
    int chunk = (n + (int)blockDim.x - 1) / (int)blockDim.x;
    int start = tid * chunk;
    int end = min(start + chunk, n);
    int s = 0;
    for (int i = start; i < end; ++i) s += g_deg[i];
    sums[tid] = s;
    __syncthreads();
    for (int o = 1; o < (int)blockDim.x; o <<= 1) {
        int t = (tid >= o) ? sums[tid - o] : 0;
        __syncthreads();
        sums[tid] += t;
        __syncthreads();
    }
    int off = sums[tid] - s;  // exclusive prefix
    for (int i = start; i < end; ++i) {
        g_row[i] = off;
        g_cursor[i] = off;
        off += g_deg[i];
    }
}

// ---------------------------------------------------------------- scatter (group src by dst)
__global__ void k_scatter(const void* __restrict__ ei, int E) {
    int e = blockIdx.x * blockDim.x + threadIdx.x;
    if (e >= E) return;
    int is64 = g_is64;
    int src = load_edge(ei, (size_t)e, is64);
    int dst = load_edge(ei, (size_t)E + e, is64);
    int pos = atomicAdd(&g_cursor[dst], 1);
    g_src_s[pos] = src;
}

// ---------------------------------------------------------------- P,Q node transforms
// warp per node, lane owns output pair (2*lane, 2*lane+1), packed f32x2.
// P gets b1 folded in.
__global__ void k_pq(const float* __restrict__ x, const float* __restrict__ W1,
                     const float* __restrict__ b1, int N) {
    __shared__ ull A2[64 * 32];  // [d][pair] : (W1a-W1b)^T, k-pairs packed
    __shared__ ull B2[64 * 32];  // [d][pair] : W1b^T
    int tid = threadIdx.x;
    for (int idx = tid; idx < 2048; idx += blockDim.x) {
        int d = idx >> 5, p = idx & 31;
        int k0 = 2 * p, k1 = 2 * p + 1;
        float w0a = W1[k0 * 128 + d], w0b = W1[k0 * 128 + 64 + d];
        float w1a = W1[k1 * 128 + d], w1b = W1[k1 * 128 + 64 + d];
        A2[idx] = pack2(w0a - w0b, w1a - w1b);
        B2[idx] = pack2(w0b, w1b);
    }
    __syncthreads();
    int lane = tid & 31;
    int warps = (gridDim.x * blockDim.x) >> 5;
    int gw = (blockIdx.x * blockDim.x + tid) >> 5;
    ull* P2 = (ull*)g_P;
    ull* Q2 = (ull*)g_Q;
    ull bias = pack2(b1[2 * lane], b1[2 * lane + 1]);
    for (int n = gw; n < N; n += warps) {
        const float* xr = x + (size_t)n * 64;
        ull accP = bias, accQ = 0ull;
#pragma unroll
        for (int d = 0; d < 64; d++) {
            float xv = __ldg(&xr[d]);
            ull x2 = pack2(xv, xv);
            fma2(accP, x2, A2[d * 32 + lane]);
            fma2(accQ, x2, B2[d * 32 + lane]);
        }
        P2[(size_t)n * 32 + lane] = accP;
        Q2[(size_t)n * 32 + lane] = accQ;
    }
}

// ---------------------------------------------------------------- main edge kernel
// warp per dst node. Lane holds W2 rows (2*lane, 2*lane+1) pair-packed in regs.
__global__ void __launch_bounds__(128, 3) k_edge(
    const float* __restrict__ b2, const float* __restrict__ W2,
    float* __restrict__ out, int N)
{
    __shared__ __align__(16) ull h_s[4][32];
    int lane = threadIdx.x & 31;
    int wid = threadIdx.x >> 5;
    ull* hsw = h_s[wid];
    const float4* hq4 = (const float4*)hsw;

    // W2 rows for this lane's output pair, packed per input dim d
    int k0 = 2 * lane, k1 = 2 * lane + 1;
    ull w[64];
    const float4* r0 = (const float4*)(W2 + k0 * 64);
    const float4* r1 = (const float4*)(W2 + k1 * 64);
#pragma unroll
    for (int t = 0; t < 16; t++) {
        float4 a = r0[t], b = r1[t];
        w[4 * t + 0] = pack2(a.x, b.x);
        w[4 * t + 1] = pack2(a.y, b.y);
        w[4 * t + 2] = pack2(a.z, b.z);
        w[4 * t + 3] = pack2(a.w, b.w);
    }
    float b2v0 = b2[k0], b2v1 = b2[k1];

    const ull* P2 = (const ull*)g_P;
    const ull* Q2 = (const ull*)g_Q;
    const unsigned FULL = 0xFFFFFFFFu;

    int gw = (blockIdx.x * blockDim.x + threadIdx.x) >> 5;
    int nwarps = (gridDim.x * blockDim.x) >> 5;

    for (int i = gw; i < N; i += nwarps) {
        int deg = g_deg[i];
        float2* orow = (float2*)(out + (size_t)i * 64);
        if (deg == 0) {
            orow[lane] = make_float2(0.f, 0.f);
            continue;
        }
        int row = g_row[i];
        ull pb2 = P2[(size_t)i * 32 + lane];
        float rm0 = -CUDART_INF_F, rm1 = -CUDART_INF_F;

        for (int base = 0; base < deg; base += 32) {
            int cnt = min(32, deg - base);
            int jv = g_src_s[row + base + min(lane, cnt - 1)];
            int j0 = __shfl_sync(FULL, jv, 0);
            ull q2 = Q2[(size_t)j0 * 32 + lane];  // prefetched
            for (int e = 0; e < cnt; e++) {
                ull q2n = 0ull;
                if (e + 1 < cnt) {  // warp-uniform branch
                    int jn = __shfl_sync(FULL, jv, e + 1);
                    q2n = Q2[(size_t)jn * 32 + lane];
                }
                // h pair for dims (2*lane, 2*lane+1)
                ull s2 = add2(pb2, q2);
                float lo, hi;
                unpack2(s2, lo, hi);
                lo = lo > 0.f ? lo : 0.01f * lo;
                hi = hi > 0.f ? hi : 0.01f * hi;
                __syncwarp();
                hsw[lane] = pack2(lo, hi);
                __syncwarp();
                // GEMV: 64 packed FMAs against register W2, h via uniform LDS
                ull a0 = 0ull, a1 = 0ull, a2 = 0ull, a3 = 0ull;
#pragma unroll
                for (int t = 0; t < 16; t++) {
                    float4 h4 = hq4[t];
                    fma2(a0, pack2(h4.x, h4.x), w[4 * t + 0]);
                    fma2(a1, pack2(h4.y, h4.y), w[4 * t + 1]);
                    fma2(a2, pack2(h4.z, h4.z), w[4 * t + 2]);
                    fma2(a3, pack2(h4.w, h4.w), w[4 * t + 3]);
                }
                a0 = add2(a0, a1);
                a2 = add2(a2, a3);
                a0 = add2(a0, a2);
                float m0, m1;
                unpack2(a0, m0, m1);
                rm0 = fmaxf(rm0, m0);
                rm1 = fmaxf(rm1, m1);
                q2 = q2n;
            }
        }
        orow[lane] = make_float2(tanhf(rm0 + b2v0), tanhf(rm1 + b2v1));
    }
}

// ---------------------------------------------------------------- launch
extern "C" void kernel_launch(void* const* d_in, const int* in_sizes, int n_in,
                              void* d_out, int out_size) {
    const float* x  = (const float*)d_in[0];
    const void*  ei = d_in[1];
    const float* W1 = (const float*)d_in[2];
    const float* b1 = (const float*)d_in[3];
    const float* W2 = (const float*)d_in[4];
    const float* b2 = (const float*)d_in[5];
    int N = in_sizes[0] / 64;
    int E = in_sizes[1] / 2;
    float* out = (float*)d_out;

    k_init<<<(N + 255) / 256, 256>>>((const int*)ei, N);
    k_hist<<<(E + 255) / 256, 256>>>(ei, E);
    k_scan<<<1, 1024>>>(N);
    k_scatter<<<(E + 255) / 256, 256>>>(ei, E);
    k_pq<<<1024, 256>>>(x, W1, b1, N);
    k_edge<<<444, 128>>>(b2, W2, out, N);
}

// round 3
// speedup vs baseline: 1.1619x; 1.0397x over previous
#include <cuda_runtime.h>
#include <math_constants.h>

// Breadth_45896020525813 — fused GNN layer (round 3):
//   P = x @ (W1a - W1b)^T + b1 ; Q = x @ W1b^T     (node-level)
//   per edge: h = leaky(P[dst]+Q[src]); msg = h@W2^T ; max over edges per dst
//   out = tanh(max + b2), empty rows -> 0
//
// k_edge: warp-per-dst CSR walk, W2 register-resident (no forced occupancy ->
// no spills), h staged pre-duplicated in smem, 2 edges per iteration,
// software-pipelined gathers. No atomics.

typedef unsigned long long ull;

#define NMAX 50000
#define EMAX 800000

__device__ float g_P[NMAX * 64];   // P + b1, pair-packed [n][32] ull view
__device__ float g_Q[NMAX * 64];
__device__ int   g_src_s[EMAX];    // src ids grouped by dst
__device__ int   g_deg[NMAX];
__device__ int   g_row[NMAX];      // CSR row start
__device__ int   g_cursor[NMAX];
__device__ int   g_is64;

__device__ __forceinline__ ull pack2(float lo, float hi) {
    ull r;
    asm("mov.b64 %0, {%1, %2};" : "=l"(r) : "f"(lo), "f"(hi));
    return r;
}
__device__ __forceinline__ void unpack2(ull v, float& lo, float& hi) {
    asm("mov.b64 {%0, %1}, %2;" : "=f"(lo), "=f"(hi) : "l"(v));
}
__device__ __forceinline__ void fma2(ull& acc, ull a, ull b) {
    asm("fma.rn.f32x2 %0, %1, %2, %0;" : "+l"(acc) : "l"(a), "l"(b));
}
__device__ __forceinline__ ull add2(ull a, ull b) {
    ull r;
    asm("add.rn.f32x2 %0, %1, %2;" : "=l"(r) : "l"(a), "l"(b));
    return r;
}

// ---------------------------------------------------------------- init
__global__ void k_init(const int* __restrict__ ei_raw, int N) {
    int idx = blockIdx.x * blockDim.x + threadIdx.x;
    if (idx < N) g_deg[idx] = 0;
    if (idx == 0) {
        int z = 0;
#pragma unroll
        for (int t = 1; t < 64; t += 2) z |= ei_raw[t];
        g_is64 = (z == 0) ? 1 : 0;
    }
}

__device__ __forceinline__ int load_edge(const void* ei, size_t pos, int is64) {
    return is64 ? (int)((const long long*)ei)[pos] : ((const int*)ei)[pos];
}

// ---------------------------------------------------------------- histogram
__global__ void k_hist(const void* __restrict__ ei, int E) {
    int e = blockIdx.x * blockDim.x + threadIdx.x;
    if (e >= E) return;
    int dst = load_edge(ei, (size_t)E + e, g_is64);
    atomicAdd(&g_deg[dst], 1);
}

// ---------------------------------------------------------------- scan (1 block)
__global__ void k_scan(int n) {
    __shared__ int sums[1024];
    int tid = threadIdx.x;
    int chunk = (n + (int)blockDim.x - 1) / (int)blockDim.x;
    int start = tid * chunk;
    int end = min(start + chunk, n);
    int s = 0;
    for (int i = start; i < end; ++i) s += g_deg[i];
    sums[tid] = s;
    __syncthreads();
    for (int o = 1; o < (int)blockDim.x; o <<= 1) {
        int t = (tid >= o) ? sums[tid - o] : 0;
        __syncthreads();
        sums[tid] += t;
        __syncthreads();
    }
    int off = sums[tid] - s;  // exclusive prefix
    for (int i = start; i < end; ++i) {
        g_row[i] = off;
        g_cursor[i] = off;
        off += g_deg[i];
    }
}

// ---------------------------------------------------------------- scatter (group src by dst)
__global__ void k_scatter(const void* __restrict__ ei, int E) {
    int e = blockIdx.x * blockDim.x + threadIdx.x;
    if (e >= E) return;
    int is64 = g_is64;
    int src = load_edge(ei, (size_t)e, is64);
    int dst = load_edge(ei, (size_t)E + e, is64);
    int pos = atomicAdd(&g_cursor[dst], 1);
    g_src_s[pos] = src;
}

// ---------------------------------------------------------------- P,Q node transforms
// warp per node, lane owns output pair (2*lane, 2*lane+1), packed f32x2.
// P gets b1 folded in.
__global__ void k_pq(const float* __restrict__ x, const float* __restrict__ W1,
                     const float* __restrict__ b1, int N) {
    __shared__ ull A2[64 * 32];  // [d][pair] : (W1a-W1b)^T, k-pairs packed
    __shared__ ull B2[64 * 32];  // [d][pair] : W1b^T
    int tid = threadIdx.x;
    for (int idx = tid; idx < 2048; idx += blockDim.x) {
        int d = idx >> 5, p = idx & 31;
        int k0 = 2 * p, k1 = 2 * p + 1;
        float w0a = W1[k0 * 128 + d], w0b = W1[k0 * 128 + 64 + d];
        float w1a = W1[k1 * 128 + d], w1b = W1[k1 * 128 + 64 + d];
        A2[idx] = pack2(w0a - w0b, w1a - w1b);
        B2[idx] = pack2(w0b, w1b);
    }
    __syncthreads();
    int lane = tid & 31;
    int warps = (gridDim.x * blockDim.x) >> 5;
    int gw = (blockIdx.x * blockDim.x + tid) >> 5;
    ull* P2 = (ull*)g_P;
    ull* Q2 = (ull*)g_Q;
    ull bias = pack2(b1[2 * lane], b1[2 * lane + 1]);
    for (int n = gw; n < N; n += warps) {
        const float4* xr4 = (const float4*)(x + (size_t)n * 64);
        ull accP = bias, accQ = 0ull;
#pragma unroll
        for (int t = 0; t < 16; t++) {
            float4 xq = __ldg(&xr4[t]);   // warp-uniform LDG.128
            int d = 4 * t;
            ull x0 = pack2(xq.x, xq.x), x1 = pack2(xq.y, xq.y);
            ull x2 = pack2(xq.z, xq.z), x3 = pack2(xq.w, xq.w);
            fma2(accP, x0, A2[(d + 0) * 32 + lane]);
            fma2(accQ, x0, B2[(d + 0) * 32 + lane]);
            fma2(accP, x1, A2[(d + 1) * 32 + lane]);
            fma2(accQ, x1, B2[(d + 1) * 32 + lane]);
            fma2(accP, x2, A2[(d + 2) * 32 + lane]);
            fma2(accQ, x2, B2[(d + 2) * 32 + lane]);
            fma2(accP, x3, A2[(d + 3) * 32 + lane]);
            fma2(accQ, x3, B2[(d + 3) * 32 + lane]);
        }
        P2[(size_t)n * 32 + lane] = accP;
        Q2[(size_t)n * 32 + lane] = accQ;
    }
}

// ---------------------------------------------------------------- main edge kernel
// warp per dst node. Lane holds W2 rows (2*lane, 2*lane+1) pair-packed in regs.
// 2 edges per iteration; h staged pre-duplicated (pack2(v,v)) in smem.
__global__ void __launch_bounds__(128) k_edge(
    const float* __restrict__ b2, const float* __restrict__ W2,
    float* __restrict__ out, int N)
{
    __shared__ __align__(16) ull h_s[4][2][64];  // [warp][edge-in-pair][dim], duplicated pairs
    int lane = threadIdx.x & 31;
    int wid = threadIdx.x >> 5;
    ull* h0w = h_s[wid][0];
    ull* h1w = h_s[wid][1];
    const ulonglong2* h0q = (const ulonglong2*)h0w;
    const ulonglong2* h1q = (const ulonglong2*)h1w;

    // W2 rows for this lane's output pair, packed per input dim d
    int k0 = 2 * lane, k1 = 2 * lane + 1;
    ull w[64];
    const float4* r0 = (const float4*)(W2 + k0 * 64);
    const float4* r1 = (const float4*)(W2 + k1 * 64);
#pragma unroll
    for (int t = 0; t < 16; t++) {
        float4 a = __ldg(&r0[t]), b = __ldg(&r1[t]);
        w[4 * t + 0] = pack2(a.x, b.x);
        w[4 * t + 1] = pack2(a.y, b.y);
        w[4 * t + 2] = pack2(a.z, b.z);
        w[4 * t + 3] = pack2(a.w, b.w);
    }
    float b2v0 = b2[k0], b2v1 = b2[k1];

    const ull* P2 = (const ull*)g_P;
    const ull* Q2 = (const ull*)g_Q;

    int gw = (blockIdx.x * blockDim.x + threadIdx.x) >> 5;
    int nwarps = (gridDim.x * blockDim.x) >> 5;

    for (int i = gw; i < N; i += nwarps) {
        int deg = g_deg[i];
        float2* orow = (float2*)(out + (size_t)i * 64);
        if (deg == 0) {
            orow[lane] = make_float2(0.f, 0.f);
            continue;
        }
        int row = g_row[i];
        int last = deg - 1;
        ull pb2 = P2[(size_t)i * 32 + lane];

        // pipeline prologue: q for pair0, j for pair1 (clamped; dups benign)
        int j0 = g_src_s[row];
        int j1 = g_src_s[row + min(1, last)];
        ull q0 = Q2[(size_t)j0 * 32 + lane];
        ull q1 = Q2[(size_t)j1 * 32 + lane];
        int j2 = g_src_s[row + min(2, last)];
        int j3 = g_src_s[row + min(3, last)];

        float rm0 = -CUDART_INF_F, rm1 = -CUDART_INF_F;

        for (int e = 0; e < deg; e += 2) {
            // prefetch j for pair e+4 (two pairs ahead)
            int j4, j5;
            if (e + 5 < deg) {                      // warp-uniform branch
                j4 = g_src_s[row + e + 4];
                j5 = g_src_s[row + e + 5];
            } else {
                j4 = g_src_s[row + min(e + 4, last)];
                j5 = j4;
            }
            // prefetch q for pair e+2 (one pair ahead)
            ull qn0 = Q2[(size_t)j2 * 32 + lane];
            ull qn1 = Q2[(size_t)j3 * 32 + lane];

            // h for both edges of this pair, duplicated into smem
            {
                ull s = add2(pb2, q0);
                float lo, hi;
                unpack2(s, lo, hi);
                lo = lo > 0.f ? lo : 0.01f * lo;
                hi = hi > 0.f ? hi : 0.01f * hi;
                ((ulonglong2*)h0w)[lane] = make_ulonglong2(pack2(lo, lo), pack2(hi, hi));
            }
            {
                ull s = add2(pb2, q1);
                float lo, hi;
                unpack2(s, lo, hi);
                lo = lo > 0.f ? lo : 0.01f * lo;
                hi = hi > 0.f ? hi : 0.01f * hi;
                ((ulonglong2*)h1w)[lane] = make_ulonglong2(pack2(lo, lo), pack2(hi, hi));
            }
            __syncwarp();

            // GEMV for both edges: 128 fma2 against register W2
            ull a00 = 0, a01 = 0, a02 = 0, a03 = 0;
            ull a10 = 0, a11 = 0, a12 = 0, a13 = 0;
#pragma unroll
            for (int t = 0; t < 16; t++) {
                ulonglong2 u0a = h0q[2 * t], u0b = h0q[2 * t + 1];
                ulonglong2 u1a = h1q[2 * t], u1b = h1q[2 * t + 1];
                fma2(a00, u0a.x, w[4 * t + 0]);
                fma2(a01, u0a.y, w[4 * t + 1]);
                fma2(a02, u0b.x, w[4 * t + 2]);
                fma2(a03, u0b.y, w[4 * t + 3]);
                fma2(a10, u1a.x, w[4 * t + 0]);
                fma2(a11, u1a.y, w[4 * t + 1]);
                fma2(a12, u1b.x, w[4 * t + 2]);
                fma2(a13, u1b.y, w[4 * t + 3]);
            }
            __syncwarp();   // reads done before next iteration's stores

            a00 = add2(a00, a01); a02 = add2(a02, a03); a00 = add2(a00, a02);
            a10 = add2(a10, a11); a12 = add2(a12, a13); a10 = add2(a10, a12);
            float m0, m1;
            unpack2(a00, m0, m1);
            rm0 = fmaxf(rm0, m0); rm1 = fmaxf(rm1, m1);
            unpack2(a10, m0, m1);
            rm0 = fmaxf(rm0, m0); rm1 = fmaxf(rm1, m1);

            q0 = qn0; q1 = qn1;
            j2 = j4;  j3 = j5;
        }
        orow[lane] = make_float2(tanhf(rm0 + b2v0), tanhf(rm1 + b2v1));
    }
}

// ---------------------------------------------------------------- launch
extern "C" void kernel_launch(void* const* d_in, const int* in_sizes, int n_in,
                              void* d_out, int out_size) {
    const float* x  = (const float*)d_in[0];
    const void*  ei = d_in[1];
    const float* W1 = (const float*)d_in[2];
    const float* b1 = (const float*)d_in[3];
    const float* W2 = (const float*)d_in[4];
    const float* b2 = (const float*)d_in[5];
    int N = in_sizes[0] / 64;
    int E = in_sizes[1] / 2;
    float* out = (float*)d_out;

    k_init<<<(N + 255) / 256, 256>>>((const int*)ei, N);
    k_hist<<<(E + 255) / 256, 256>>>(ei, E);
    k_scan<<<1, 1024>>>(N);
    k_scatter<<<(E + 255) / 256, 256>>>(ei, E);
    k_pq<<<592, 256>>>(x, W1, b1, N);
    k_edge<<<296, 128>>>(b2, W2, out, N);
}

// round 4
// speedup vs baseline: 1.6904x; 1.4549x over previous
#include <cuda_runtime.h>
#include <math_constants.h>

// Breadth_45896020525813 — fused GNN layer (round 4):
//   P = x @ (W1a - W1b)^T + b1 ; Q = x @ W1b^T     (node-level)
//   per edge: h = leaky(P[dst]+Q[src]); msg = h@W2^T ; max over edges per dst
//   out = tanh(max + b2), empty rows -> 0

typedef unsigned long long ull;

#define NMAX 50000
#define EMAX 800000
#define SCAN_B 512

__device__ float g_P[NMAX * 64];   // P + b1, pair-packed [n][32] ull view
__device__ float g_Q[NMAX * 64];
__device__ int   g_src_s[EMAX];    // src ids grouped by dst
__device__ int   g_deg[NMAX];
__device__ int2  g_rowdeg[NMAX];   // {row start, degree}
__device__ int   g_cursor[NMAX];
__device__ int   g_part[128];
__device__ int   g_is64;

__device__ __forceinline__ ull pack2(float lo, float hi) {
    ull r;
    asm("mov.b64 %0, {%1, %2};" : "=l"(r) : "f"(lo), "f"(hi));
    return r;
}
__device__ __forceinline__ void unpack2(ull v, float& lo, float& hi) {
    asm("mov.b64 {%0, %1}, %2;" : "=f"(lo), "=f"(hi) : "l"(v));
}
__device__ __forceinline__ void fma2(ull& acc, ull a, ull b) {
    asm("fma.rn.f32x2 %0, %1, %2, %0;" : "+l"(acc) : "l"(a), "l"(b));
}
__device__ __forceinline__ ull add2(ull a, ull b) {
    ull r;
    asm("add.rn.f32x2 %0, %1, %2;" : "=l"(r) : "l"(a), "l"(b));
    return r;
}

// ---------------------------------------------------------------- init
__global__ void k_init(const int* __restrict__ ei_raw, int N) {
    int idx = blockIdx.x * blockDim.x + threadIdx.x;
    if (idx < N) g_deg[idx] = 0;
    if (idx == 0) {
        int z = 0;
#pragma unroll
        for (int t = 1; t < 64; t += 2) z |= ei_raw[t];
        g_is64 = (z == 0) ? 1 : 0;
    }
}

// ---------------------------------------------------------------- histogram (2 edges/thread)
__global__ void k_hist(const void* __restrict__ ei, int E) {
    int e = 2 * (blockIdx.x * blockDim.x + threadIdx.x);
    if (e >= E) return;
    int d0, d1;
    if (g_is64) {
        longlong2 d = ((const longlong2*)ei)[(E + e) >> 1];
        d0 = (int)d.x; d1 = (int)d.y;
    } else {
        int2 d = ((const int2*)ei)[(E + e) >> 1];
        d0 = d.x; d1 = d.y;
    }
    atomicAdd(&g_deg[d0], 1);
    if (e + 1 < E) atomicAdd(&g_deg[d1], 1);
}

// ---------------------------------------------------------------- 3-phase scan
__device__ __forceinline__ int warp_iscan(int v, int lane) {
#pragma unroll
    for (int o = 1; o < 32; o <<= 1) {
        int t = __shfl_up_sync(0xFFFFFFFFu, v, o);
        if (lane >= o) v += t;
    }
    return v;
}

__global__ void k_scanA(int N) {
    int idx = blockIdx.x * SCAN_B + threadIdx.x;
    int v = (idx < N) ? g_deg[idx] : 0;
    int lane = threadIdx.x & 31, wid = threadIdx.x >> 5;
#pragma unroll
    for (int o = 16; o > 0; o >>= 1) v += __shfl_down_sync(0xFFFFFFFFu, v, o);
    __shared__ int ws[SCAN_B / 32];
    if (lane == 0) ws[wid] = v;
    __syncthreads();
    if (threadIdx.x < SCAN_B / 32) {
        int t = ws[threadIdx.x];
#pragma unroll
        for (int o = 8; o > 0; o >>= 1) t += __shfl_down_sync(0xFFFFu, t, o);
        if (threadIdx.x == 0) g_part[blockIdx.x] = t;
    }
}

__global__ void k_scanB(int nblk) {
    int t = threadIdx.x, lane = t & 31, wid = t >> 5;
    int v = (t < nblk) ? g_part[t] : 0;
    int s = warp_iscan(v, lane);
    __shared__ int ws[4];
    if (lane == 31) ws[wid] = s;
    __syncthreads();
    int add = 0;
    for (int k = 0; k < wid; k++) add += ws[k];
    if (t < nblk) g_part[t] = s - v + add;  // exclusive
}

__global__ void k_scanC(int N) {
    int idx = blockIdx.x * SCAN_B + threadIdx.x;
    int v = (idx < N) ? g_deg[idx] : 0;
    int lane = threadIdx.x & 31, wid = threadIdx.x >> 5;
    int s = warp_iscan(v, lane);
    __shared__ int ws[SCAN_B / 32];
    if (lane == 31) ws[wid] = s;
    __syncthreads();
    if (threadIdx.x < 32) {
        int t = (threadIdx.x < SCAN_B / 32) ? ws[threadIdx.x] : 0;
        t = warp_iscan(t, threadIdx.x);
        if (threadIdx.x < SCAN_B / 32) ws[threadIdx.x] = t;
    }
    __syncthreads();
    int wexcl = (wid > 0) ? ws[wid - 1] : 0;
    int off = g_part[blockIdx.x] + wexcl + (s - v);
    if (idx < N) {
        g_rowdeg[idx] = make_int2(off, v);
        g_cursor[idx] = off;
    }
}

// ---------------------------------------------------------------- scatter (2 edges/thread)
__global__ void k_scatter(const void* __restrict__ ei, int E) {
    int e = 2 * (blockIdx.x * blockDim.x + threadIdx.x);
    if (e >= E) return;
    int s0, s1, d0, d1;
    if (g_is64) {
        longlong2 s = ((const longlong2*)ei)[e >> 1];
        longlong2 d = ((const longlong2*)ei)[(E + e) >> 1];
        s0 = (int)s.x; s1 = (int)s.y; d0 = (int)d.x; d1 = (int)d.y;
    } else {
        int2 s = ((const int2*)ei)[e >> 1];
        int2 d = ((const int2*)ei)[(E + e) >> 1];
        s0 = s.x; s1 = s.y; d0 = d.x; d1 = d.y;
    }
    int p0 = atomicAdd(&g_cursor[d0], 1);
    g_src_s[p0] = s0;
    if (e + 1 < E) {
        int p1 = atomicAdd(&g_cursor[d1], 1);
        g_src_s[p1] = s1;
    }
}

// ---------------------------------------------------------------- P,Q node transforms
// warp per 4 nodes per iteration; lane owns output pair (2*lane, 2*lane+1).
__global__ void k_pq(const float* __restrict__ x, const float* __restrict__ W1,
                     const float* __restrict__ b1, int N) {
    __shared__ ull A2[64 * 32];  // [d][pair] : (W1a-W1b)^T, k-pairs packed
    __shared__ ull B2[64 * 32];  // [d][pair] : W1b^T
    int tid = threadIdx.x;
    for (int idx = tid; idx < 2048; idx += blockDim.x) {
        int d = idx >> 5, p = idx & 31;
        int k0 = 2 * p, k1 = 2 * p + 1;
        float w0a = W1[k0 * 128 + d], w0b = W1[k0 * 128 + 64 + d];
        float w1a = W1[k1 * 128 + d], w1b = W1[k1 * 128 + 64 + d];
        A2[idx] = pack2(w0a - w0b, w1a - w1b);
        B2[idx] = pack2(w0b, w1b);
    }
    __syncthreads();
    int lane = tid & 31;
    int warps = (gridDim.x * blockDim.x) >> 5;
    int gw = (blockIdx.x * blockDim.x + tid) >> 5;
    ull* P2 = (ull*)g_P;
    ull* Q2 = (ull*)g_Q;
    ull bias = pack2(b1[2 * lane], b1[2 * lane + 1]);
    int Nlast = N - 1;
    for (int g = gw; g * 4 < N; g += warps) {
        int n0 = min(4 * g + 0, Nlast), n1 = min(4 * g + 1, Nlast);
        int n2 = min(4 * g + 2, Nlast), n3 = min(4 * g + 3, Nlast);
        const float4* x0 = (const float4*)(x + (size_t)n0 * 64);
        const float4* x1 = (const float4*)(x + (size_t)n1 * 64);
        const float4* x2 = (const float4*)(x + (size_t)n2 * 64);
        const float4* x3 = (const float4*)(x + (size_t)n3 * 64);
        ull p0 = bias, p1 = bias, p2 = bias, p3 = bias;
        ull q0 = 0, q1 = 0, q2 = 0, q3 = 0;
#pragma unroll
        for (int t = 0; t < 16; t++) {
            float4 a0 = __ldg(&x0[t]), a1 = __ldg(&x1[t]);
            float4 a2 = __ldg(&x2[t]), a3 = __ldg(&x3[t]);
#pragma unroll
            for (int u = 0; u < 4; u++) {
                int d = 4 * t + u;
                ull wA = A2[d * 32 + lane], wB = B2[d * 32 + lane];
                float v0 = (u == 0) ? a0.x : (u == 1) ? a0.y : (u == 2) ? a0.z : a0.w;
                float v1 = (u == 0) ? a1.x : (u == 1) ? a1.y : (u == 2) ? a1.z : a1.w;
                float v2 = (u == 0) ? a2.x : (u == 1) ? a2.y : (u == 2) ? a2.z : a2.w;
                float v3 = (u == 0) ? a3.x : (u == 1) ? a3.y : (u == 2) ? a3.z : a3.w;
                ull d0 = pack2(v0, v0), d1 = pack2(v1, v1);
                ull d2 = pack2(v2, v2), d3 = pack2(v3, v3);
                fma2(p0, d0, wA); fma2(q0, d0, wB);
                fma2(p1, d1, wA); fma2(q1, d1, wB);
                fma2(p2, d2, wA); fma2(q2, d2, wB);
                fma2(p3, d3, wA); fma2(q3, d3, wB);
            }
        }
        P2[(size_t)n0 * 32 + lane] = p0; Q2[(size_t)n0 * 32 + lane] = q0;
        P2[(size_t)n1 * 32 + lane] = p1; Q2[(size_t)n1 * 32 + lane] = q1;
        P2[(size_t)n2 * 32 + lane] = p2; Q2[(size_t)n2 * 32 + lane] = q2;
        P2[(size_t)n3 * 32 + lane] = p3; Q2[(size_t)n3 * 32 + lane] = q3;
    }
}

// ---------------------------------------------------------------- main edge kernel
// warp per dst node, cross-node software pipeline, double-buffered h staging
// (1 syncwarp / edge-pair), W2 register-resident.
__global__ void __launch_bounds__(128) k_edge(
    const float* __restrict__ b2, const float* __restrict__ W2,
    float* __restrict__ out, int N, int E)
{
    __shared__ __align__(16) ull h_s[4][2][2][64];  // [warp][buf][edge01][dup dims]
    int lane = threadIdx.x & 31;
    int wid = threadIdx.x >> 5;

    // W2 rows for this lane's output pair, packed per input dim d
    int k0 = 2 * lane, k1 = 2 * lane + 1;
    ull w[64];
    const float4* r0 = (const float4*)(W2 + k0 * 64);
    const float4* r1 = (const float4*)(W2 + k1 * 64);
#pragma unroll
    for (int t = 0; t < 16; t++) {
        float4 a = __ldg(&r0[t]), b = __ldg(&r1[t]);
        w[4 * t + 0] = pack2(a.x, b.x);
        w[4 * t + 1] = pack2(a.y, b.y);
        w[4 * t + 2] = pack2(a.z, b.z);
        w[4 * t + 3] = pack2(a.w, b.w);
    }
    float b2v0 = b2[k0], b2v1 = b2[k1];

    const ull* P2 = (const ull*)g_P;
    const ull* Q2 = (const ull*)g_Q;
    int Elast = E - 1;

    int gw = (blockIdx.x * blockDim.x + threadIdx.x) >> 5;
    int nwarps = (gridDim.x * blockDim.x) >> 5;

    // -------- node-level software pipeline prologue
    int i = gw;
    bool valid = (i < N);
    int2 rd = valid ? g_rowdeg[i] : make_int2(0, 0);
    int row = rd.x, deg = rd.y;
    int jA = g_src_s[min(row, Elast)];
    int jB = g_src_s[min(row + (deg > 1 ? 1 : 0), Elast)];
    ull pb = 0, qA = 0, qB = 0;
    if (valid) {
        pb = P2[(size_t)i * 32 + lane];
        qA = Q2[(size_t)jA * 32 + lane];
        qB = Q2[(size_t)jB * 32 + lane];
    }

    while (valid) {
        // prefetch next node's metadata + first gathers (overlaps edge loop)
        int inext = i + nwarps;
        bool vn = (inext < N);
        int2 rdn = vn ? g_rowdeg[inext] : make_int2(0, 0);
        int rown = rdn.x, degn = rdn.y;
        int jn0 = g_src_s[min(rown, Elast)];
        int jn1 = g_src_s[min(rown + (degn > 1 ? 1 : 0), Elast)];
        ull pbn = 0, qn0 = 0, qn1 = 0;
        if (vn) {
            pbn = P2[(size_t)inext * 32 + lane];
            qn0 = Q2[(size_t)jn0 * 32 + lane];
            qn1 = Q2[(size_t)jn1 * 32 + lane];
        }

        float2* orow = (float2*)(out + (size_t)i * 64);
        if (deg == 0) {
            orow[lane] = make_float2(0.f, 0.f);
        } else {
            int last = deg - 1;
            ull q0 = qA, q1 = qB;
            int j2 = g_src_s[row + min(2, last)];
            int j3 = g_src_s[row + min(3, last)];
            float rm0 = -CUDART_INF_F, rm1 = -CUDART_INF_F;
            int buf = 0;

            for (int e = 0; e < deg; e += 2) {
                // j prefetch: two pairs ahead
                int j4, j5;
                if (e + 5 < deg) {
                    j4 = g_src_s[row + e + 4];
                    j5 = g_src_s[row + e + 5];
                } else {
                    j4 = g_src_s[row + min(e + 4, last)];
                    j5 = j4;
                }
                // q prefetch: one pair ahead
                ull qp0 = Q2[(size_t)j2 * 32 + lane];
                ull qp1 = Q2[(size_t)j3 * 32 + lane];

                ull* h0w = h_s[wid][buf][0];
                ull* h1w = h_s[wid][buf][1];
                {
                    ull s = add2(pb, q0);
                    float lo, hi;
                    unpack2(s, lo, hi);
                    lo = fmaxf(lo, 0.01f * lo);
                    hi = fmaxf(hi, 0.01f * hi);
                    ((ulonglong2*)h0w)[lane] = make_ulonglong2(pack2(lo, lo), pack2(hi, hi));
                }
                {
                    ull s = add2(pb, q1);
                    float lo, hi;
                    unpack2(s, lo, hi);
                    lo = fmaxf(lo, 0.01f * lo);
                    hi = fmaxf(hi, 0.01f * hi);
                    ((ulonglong2*)h1w)[lane] = make_ulonglong2(pack2(lo, lo), pack2(hi, hi));
                }
                __syncwarp();   // single barrier: separates read(i-2) from store(i)

                const ulonglong2* h0q = (const ulonglong2*)h0w;
                const ulonglong2* h1q = (const ulonglong2*)h1w;
                ull a00 = 0, a01 = 0, a02 = 0, a03 = 0;
                ull a10 = 0, a11 = 0, a12 = 0, a13 = 0;
#pragma unroll
                for (int t = 0; t < 16; t++) {
                    ulonglong2 u0a = h0q[2 * t], u0b = h0q[2 * t + 1];
                    ulonglong2 u1a = h1q[2 * t], u1b = h1q[2 * t + 1];
                    fma2(a00, u0a.x, w[4 * t + 0]);
                    fma2(a01, u0a.y, w[4 * t + 1]);
                    fma2(a02, u0b.x, w[4 * t + 2]);
                    fma2(a03, u0b.y, w[4 * t + 3]);
                    fma2(a10, u1a.x, w[4 * t + 0]);
                    fma2(a11, u1a.y, w[4 * t + 1]);
                    fma2(a12, u1b.x, w[4 * t + 2]);
                    fma2(a13, u1b.y, w[4 * t + 3]);
                }

                a00 = add2(a00, a01); a02 = add2(a02, a03); a00 = add2(a00, a02);
                a10 = add2(a10, a11); a12 = add2(a12, a13); a10 = add2(a10, a12);
                float m0, m1;
                unpack2(a00, m0, m1);
                rm0 = fmaxf(rm0, m0); rm1 = fmaxf(rm1, m1);
                unpack2(a10, m0, m1);
                rm0 = fmaxf(rm0, m0); rm1 = fmaxf(rm1, m1);

                q0 = qp0; q1 = qp1;
                j2 = j4;  j3 = j5;
                buf ^= 1;
            }
            orow[lane] = make_float2(tanhf(rm0 + b2v0), tanhf(rm1 + b2v1));
        }

        // rotate pipeline
        i = inext; valid = vn;
        row = rown; deg = degn;
        pb = pbn; qA = qn0; qB = qn1;
    }
}

// ---------------------------------------------------------------- launch
extern "C" void kernel_launch(void* const* d_in, const int* in_sizes, int n_in,
                              void* d_out, int out_size) {
    const float* x  = (const float*)d_in[0];
    const void*  ei = d_in[1];
    const float* W1 = (const float*)d_in[2];
    const float* b1 = (const float*)d_in[3];
    const float* W2 = (const float*)d_in[4];
    const float* b2 = (const float*)d_in[5];
    int N = in_sizes[0] / 64;
    int E = in_sizes[1] / 2;
    float* out = (float*)d_out;
    int nblk = (N + SCAN_B - 1) / SCAN_B;

    k_init<<<(N + 255) / 256, 256>>>((const int*)ei, N);
    k_hist<<<(E / 2 + 255) / 256, 256>>>(ei, E);
    k_scanA<<<nblk, SCAN_B>>>(N);
    k_scanB<<<1, 128>>>(nblk);
    k_scanC<<<nblk, SCAN_B>>>(N);
    k_scatter<<<(E / 2 + 255) / 256, 256>>>(ei, E);
    k_pq<<<296, 256>>>(x, W1, b1, N);
    k_edge<<<296, 128>>>(b2, W2, out, N, E);
}